// round 8
// baseline (speedup 1.0000x reference)
#include <cuda_runtime.h>
#include <math.h>

// ---------------- problem constants ----------------
#define NB     256                 // graphs per batch
#define G      400                 // nodes per graph
#define DEG    32                  // avg degree
#define INDIM  400
#define D1     32
#define KSEL   200                 // top-k kept nodes
#define EPG    (G*DEG)             // 12800 edges per graph
#define NN     (NB*G)              // 102400 nodes
#define ETOTLL ((long long)NB*(long long)EPG)  // 3276800 edges
#define SLOPE  0.2f
#define BN_SCL 0.99999499987f      // 1/sqrt(1+1e-5)
#define CAP    64                  // per-dst bin capacity (max deg ~60 incl self)

// output layout (float32): logits[NB*2] | pool_w[32] | sig(vals)[NB*K] | perm[NB*K]
#define OFF_POOLW (NB*2)               // 512
#define OFF_SIG   (OFF_POOLW + D1)     // 544
#define OFF_PERM  (OFF_SIG + NB*KSEL)  // 51744

// ---------------- scratch (module-static, no runtime alloc) ----------------
__device__ float g_h[(size_t)NN*D1];     // 13.1 MB
__device__ float g_out_buf[(size_t)NN*D1];
__device__ float g_as[NN];
__device__ float g_ad[NN];

// ---------------- index dtype handling ----------------
__device__ __forceinline__ int detect_is64(const void* p) {
    const int* w = (const int*)p;
    int any = 0;
#pragma unroll
    for (int j = 1; j <= 15; j += 2) any |= w[j];
    return any == 0;
}
__device__ __forceinline__ int load_idx(const void* p, long long i, int is64) {
    return is64 ? (int)((const long long*)p)[i] : ((const int*)p)[i];
}

// ---------------- f32x2 + cp.async helpers ----------------
typedef unsigned long long u64t;
__device__ __forceinline__ void fma2(u64t& d, u64t a, u64t b) {
    asm volatile("fma.rn.f32x2 %0, %1, %2, %0;" : "+l"(d) : "l"(a), "l"(b));
}
__device__ __forceinline__ u64t pack2(float lo, float hi) {
    u64t r;
    asm("mov.b64 %0, {%1, %2};" : "=l"(r) : "f"(lo), "f"(hi));
    return r;
}
__device__ __forceinline__ void unpack2(u64t v, float& lo, float& hi) {
    asm("mov.b64 {%0, %1}, %2;" : "=f"(lo), "=f"(hi) : "l"(v));
}
__device__ __forceinline__ void cpa4(float* s, const float* g) {
    unsigned sa = (unsigned)__cvta_generic_to_shared(s);
    asm volatile("cp.async.ca.shared.global [%0], [%1], 4;" :: "r"(sa), "l"(g));
}
__device__ __forceinline__ void cpa16(void* s, const void* g) {
    unsigned sa = (unsigned)__cvta_generic_to_shared(s);
    asm volatile("cp.async.cg.shared.global [%0], [%1], 16;" :: "r"(sa), "l"(g));
}
__device__ __forceinline__ void cpa_commit() {
    asm volatile("cp.async.commit_group;");
}
template <int N> __device__ __forceinline__ void cpa_wait() {
    asm volatile("cp.async.wait_group %0;" :: "n"(N));
}

// ============================================================================
// K1: h = x @ W (+ a_src, a_dst).  FFMA2 + cp.async, regridded:
// 128 rows/CTA, 128 threads -> 800 CTAs, 6+ CTAs/SM, single balanced wave.
// ============================================================================
#define KC    16
#define ASTR  130
__global__ __launch_bounds__(128) void k_gemm(
    const float* __restrict__ x, const float* __restrict__ W,
    const float* __restrict__ att_src, const float* __restrict__ att_dst)
{
    __shared__ float shA[2][KC*ASTR];   // 16.6 KB
    __shared__ float shB[2][KC*32];     //  4.0 KB

    const int t  = threadIdx.x;
    const int tc = t & 7;               // cols [tc*4, tc*4+4)
    const int tr = t >> 3;              // rows [tr*8, tr*8+8), tr in 0..15
    const size_t row0 = (size_t)blockIdx.x * 128;

    // A loader: kk = t&15, rows lr + 8*j (j<16)
    const int lkk = t & 15, lr = t >> 4;            // lr in 0..7
    const float* xbase = x + (row0 + lr) * INDIM + lkk;
    // B loader: kk = t>>3 (0..15), cols bc..bc+3
    const int bkk = t >> 3, bc = (t & 7) * 4;

    u64t acc[4][4];
#pragma unroll
    for (int r = 0; r < 4; ++r)
#pragma unroll
        for (int c = 0; c < 4; ++c) acc[r][c] = 0ull;

    // prologue: chunk 0 -> buf 0
    {
#pragma unroll
        for (int j = 0; j < 16; ++j)
            cpa4(&shA[0][lkk*ASTR + lr + 8*j], xbase + (size_t)(8*j) * INDIM);
        cpa16(&shB[0][bkk*32 + bc], W + (size_t)bkk * 32 + bc);
        cpa_commit();
    }

    int buf = 0;
#pragma unroll 1
    for (int c = 0; c < INDIM/KC; ++c) {
        if (c + 1 < INDIM/KC) {
            const float* src = xbase + (size_t)(c + 1) * KC;
#pragma unroll
            for (int j = 0; j < 16; ++j)
                cpa4(&shA[buf^1][lkk*ASTR + lr + 8*j], src + (size_t)(8*j) * INDIM);
            cpa16(&shB[buf^1][bkk*32 + bc], W + (size_t)((c+1)*KC + bkk) * 32 + bc);
            cpa_commit();
            cpa_wait<1>();
        } else {
            cpa_wait<0>();
        }
        __syncthreads();

        const float* A = shA[buf];
        const float* B = shB[buf];
#pragma unroll
        for (int kk = 0; kk < KC; ++kk) {
            float4 b = *(const float4*)(B + kk*32 + tc*4);
            u64t bp0 = pack2(b.x, b.x);
            u64t bp1 = pack2(b.y, b.y);
            u64t bp2 = pack2(b.z, b.z);
            u64t bp3 = pack2(b.w, b.w);
            const float* Ak = A + kk*ASTR + tr*8;
#pragma unroll
            for (int r = 0; r < 4; ++r) {
                u64t a = *(const u64t*)(Ak + 2*r);
                fma2(acc[r][0], a, bp0);
                fma2(acc[r][1], a, bp1);
                fma2(acc[r][2], a, bp2);
                fma2(acc[r][3], a, bp3);
            }
        }
        __syncthreads();
        buf ^= 1;
    }

    float4 aS = ((const float4*)att_src)[tc];
    float4 aD = ((const float4*)att_dst)[tc];
#pragma unroll
    for (int r = 0; r < 4; ++r) {
        float l0, h0, l1, h1, l2, h2, l3, h3;
        unpack2(acc[r][0], l0, h0);
        unpack2(acc[r][1], l1, h1);
        unpack2(acc[r][2], l2, h2);
        unpack2(acc[r][3], l3, h3);
#pragma unroll
        for (int half = 0; half < 2; ++half) {
            float v0 = half ? h0 : l0, v1 = half ? h1 : l1;
            float v2 = half ? h2 : l2, v3 = half ? h3 : l3;
            size_t row = row0 + tr*8 + 2*r + half;
            *(float4*)&g_h[row*D1 + tc*4] = make_float4(v0, v1, v2, v3);
            float ps = v0*aS.x + v1*aS.y + v2*aS.z + v3*aS.w;
            float pd = v0*aD.x + v1*aD.y + v2*aD.z + v3*aD.w;
#pragma unroll
            for (int d = 4; d >= 1; d >>= 1) {
                ps += __shfl_down_sync(0xffffffffu, ps, d, 8);
                pd += __shfl_down_sync(0xffffffffu, pd, d, 8);
            }
            if (tc == 0) { g_as[row] = ps; g_ad[row] = pd; }
        }
    }
}

// ============================================================================
// K2: per-graph GAT + TopK + MLP. Quarter-autonomous aggregation (disjoint
// 8-lane masks, no cross-quarter coordination, one den reduce per dst).
// ============================================================================
#define O_H    0        // 12800 f
#define O_SRC  12800    // 400*CAP u16 = 12800 words
#define O_CNT  25600    // 400 i
#define O_AS   26000    // 400 f
#define O_AD   26400    // 400 f
#define O_SV   26800    // 512 f
#define O_SI   27312    // 512 i
// aliases (valid after aggregation finishes with sh_src):
#define O_PM   12800    // 512 f
#define O_PS   13312    // 512 f
#define O_Z    13824    // 64 f
#define O_Z1   13888    // 32 f
#define O_Z2   13920    // 8 f
#define SMEM_WORDS 27824
#define SMEM_BYTES (SMEM_WORDS*4)

__global__ __launch_bounds__(512, 2) void k_graph(
    const void* __restrict__ edge_index,
    const float* __restrict__ gat_bias, const float* __restrict__ pool_w,
    const float* __restrict__ fc1_w, const float* __restrict__ fc1_b,
    const float* __restrict__ bn1_g, const float* __restrict__ bn1_b,
    const float* __restrict__ fc2_w, const float* __restrict__ fc2_b,
    const float* __restrict__ bn2_g, const float* __restrict__ bn2_b,
    const float* __restrict__ fc3_w, const float* __restrict__ fc3_b,
    float* __restrict__ out)
{
    extern __shared__ float sm[];
    float* sh_h   = sm + O_H;
    unsigned short* sh_src = (unsigned short*)(sm + O_SRC);
    int*   sh_cnt = (int*)(sm + O_CNT);
    float* sh_as  = sm + O_AS;
    float* sh_ad  = sm + O_AD;
    float* sh_sv  = sm + O_SV;
    int*   sh_si  = (int*)(sm + O_SI);
    float* sh_pm  = sm + O_PM;
    float* sh_ps  = sm + O_PS;
    float* sh_z   = sm + O_Z;
    float* sh_z1  = sm + O_Z1;
    float* sh_z2  = sm + O_Z2;

    const int b    = blockIdx.x;
    const int t    = threadIdx.x;
    const int lane = t & 31;
    const int w    = t >> 5;
    const int qu   = lane >> 3;    // quarter 0..3
    const int ql   = lane & 7;     // lane in quarter
    const int base = b * G;
    const int is64 = detect_is64(edge_index);
    const long long e0 = (long long)b * EPG;
    const unsigned FULL = 0xffffffffu;
    const unsigned qmask = 0xFFu << (qu * 8);

    // ---- phase 1: h staging via cp.async; init cnt/as/ad/self ----
    {
        const float4* H4 = (const float4*)(g_h + (size_t)base * D1);
        float4* S4 = (float4*)sh_h;
        for (int i = t; i < G*D1/4; i += 512) cpa16(&S4[i], &H4[i]);
        cpa_commit();
        for (int i = t; i < G; i += 512) {
            sh_as[i] = g_as[base + i];
            sh_ad[i] = g_ad[base + i];
            sh_cnt[i] = 1;
            sh_src[i * CAP] = (unsigned short)i;   // self loop in slot 0
        }
    }
    __syncthreads();

    // ---- phase 2: single-pass binned scatter (overlaps h cp.async) ----
    for (int i = t; i < EPG; i += 512) {
        int s = load_idx(edge_index, e0 + i, is64) - base;
        int d = load_idx(edge_index, ETOTLL + e0 + i, is64) - base;
        int p = atomicAdd(&sh_cnt[d], 1) & (CAP - 1);
        sh_src[d * CAP + p] = (unsigned short)s;
    }
    cpa_wait<0>();
    __syncthreads();

    // ---- phase 3: fused softmax+aggregation+score, quarter-autonomous ----
    {
        float pwl = pool_w[lane];
        float n2 = pwl * pwl;
#pragma unroll
        for (int d = 16; d >= 1; d >>= 1) n2 += __shfl_xor_sync(FULL, n2, d);
        float invn = rsqrtf(n2);
        float4 pw4 = *(const float4*)&pool_w[4*ql];
        float4 gb4 = *(const float4*)&gat_bias[4*ql];

        for (int vq = 4*w; vq < G; vq += 64) {
            int v = vq + qu;
            int s1 = sh_cnt[v]; if (s1 > CAP) s1 = CAP;
            float ad = sh_ad[v];
            const unsigned short* srcp = sh_src + v * CAP;
            u64t accA = 0ull, accB = 0ull;
            float denl = 0.f;
            int nch = (s1 + 7) >> 3;
            for (int c = 0; c < nch; ++c) {
                int i = (c << 3) + ql;
                float alpha = 0.f; int s = 0;
                if (i < s1) {
                    s = srcp[i];
                    float e = sh_as[s] + ad;
                    e = (e > 0.f) ? e : SLOPE * e;
                    alpha = __expf(e);
                }
                denl += alpha;
                int rem = s1 - (c << 3);
                int n = rem > 8 ? 8 : rem;
                for (int ii = 0; ii < n; ++ii) {
                    float a = __shfl_sync(qmask, alpha, ii, 8);
                    int  ss = __shfl_sync(qmask, s, ii, 8);
                    u64t a2 = pack2(a, a);
                    ulonglong2 hv = *(const ulonglong2*)&sh_h[(ss << 5) + (ql << 2)];
                    fma2(accA, hv.x, a2);
                    fma2(accB, hv.y, a2);
                }
            }
            float den = denl;
            den += __shfl_xor_sync(qmask, den, 4, 8);
            den += __shfl_xor_sync(qmask, den, 2, 8);
            den += __shfl_xor_sync(qmask, den, 1, 8);
            float inv = 1.f / den;
            u64t i2 = pack2(inv, inv);
            u64t oA = pack2(gb4.x, gb4.y); fma2(oA, accA, i2);
            u64t oB = pack2(gb4.z, gb4.w); fma2(oB, accB, i2);
            float o0, o1, o2v, o3;
            unpack2(oA, o0, o1); unpack2(oB, o2v, o3);
            *(float4*)&g_out_buf[(size_t)(base + v) * D1 + (ql << 2)] =
                make_float4(o0, o1, o2v, o3);
            float p = o0*pw4.x + o1*pw4.y + o2v*pw4.z + o3*pw4.w;
            p += __shfl_xor_sync(qmask, p, 4, 8);
            p += __shfl_xor_sync(qmask, p, 2, 8);
            p += __shfl_xor_sync(qmask, p, 1, 8);
            if (ql == 0) {
                float sc = p * invn;
                sh_sv[v] = 1.f / (1.f + __expf(-sc));
                sh_si[v] = v;
            }
        }
    }
    if (t >= G) { sh_sv[t] = -1.f; sh_si[t] = t; }
    __syncthreads();

    // ---- bitonic sort, 512, descending value / ascending index ----
    for (int k = 2; k <= 512; k <<= 1) {
        for (int j = k >> 1; j > 0; j >>= 1) {
            int ixj = t ^ j;
            if (ixj > t) {
                float va = sh_sv[t], vb = sh_sv[ixj];
                int   ia = sh_si[t], ib = sh_si[ixj];
                bool before = (va > vb) || (va == vb && ia < ib);
                bool doswap = ((t & k) == 0) ? !before : before;
                if (doswap) {
                    sh_sv[t] = vb; sh_sv[ixj] = va;
                    sh_si[t] = ib; sh_si[ixj] = ia;
                }
            }
            __syncthreads();
        }
    }

    // ---- emit sig(vals) and perm ----
    for (int i = t; i < KSEL; i += 512) {
        float v = sh_sv[i];
        out[OFF_SIG  + b * KSEL + i] = 1.f / (1.f + __expf(-v));
        out[OFF_PERM + b * KSEL + i] = (float)(sh_si[i] + base);
    }

    // ---- global max/mean pool over selected scaled rows ----
    {
        float mx = -1e30f, smv = 0.f;
        for (int j = w; j < KSEL; j += 16) {
            float wt = sh_sv[j];
            float val = g_out_buf[(size_t)(base + sh_si[j]) * D1 + lane] * wt;
            mx = fmaxf(mx, val);
            smv += val;
        }
        sh_pm[w * 32 + lane] = mx;
        sh_ps[w * 32 + lane] = smv;
    }
    __syncthreads();
    if (t < D1) {
        float mx = -1e30f, smv = 0.f;
#pragma unroll
        for (int j = 0; j < 16; ++j) {
            mx = fmaxf(mx, sh_pm[j * 32 + t]);
            smv += sh_ps[j * 32 + t];
        }
        sh_z[t]      = mx;
        sh_z[D1 + t] = smv * (1.f / (float)KSEL);
    }
    __syncthreads();

    // ---- MLP tail (warp 0) ----
    if (w == 0) {
        float acc = fc1_b[lane];
        for (int i = 0; i < 2*D1; ++i) acc += sh_z[i] * fc1_w[i * D1 + lane];
        acc = fmaxf(acc, 0.f);
        acc = acc * (bn1_g[lane] * BN_SCL) + bn1_b[lane];
        sh_z1[lane] = acc;
        __syncwarp();
        if (lane < 8) {
            float y = fc2_b[lane];
            for (int i = 0; i < D1; ++i) y += sh_z1[i] * fc2_w[i * 8 + lane];
            y = fmaxf(y, 0.f);
            y = y * (bn2_g[lane] * BN_SCL) + bn2_b[lane];
            sh_z2[lane] = y;
        }
        __syncwarp();
        if (lane < 2) {
            float y = fc3_b[lane];
            for (int i = 0; i < 8; ++i) y += sh_z2[i] * fc3_w[i * 2 + lane];
            float other = __shfl_xor_sync(0x3u, y, 1, 2);
            float m = fmaxf(y, other);
            float lse = m + logf(expf(y - m) + expf(other - m));
            out[b * 2 + lane] = y - lse;
        }
    }

    if (b == 0 && t < D1) out[OFF_POOLW + t] = pool_w[t];
}

// ============================================================================
extern "C" void kernel_launch(void* const* d_in, const int* in_sizes, int n_in,
                              void* d_out, int out_size)
{
    const float* x        = (const float*)d_in[0];
    const void*  edge_idx = d_in[1];
    const float* W        = (const float*)d_in[4];
    const float* att_src  = (const float*)d_in[5];
    const float* att_dst  = (const float*)d_in[6];
    const float* gat_bias = (const float*)d_in[7];
    const float* pool_w   = (const float*)d_in[8];
    const float* fc1_w    = (const float*)d_in[9];
    const float* fc1_b    = (const float*)d_in[10];
    const float* bn1_g    = (const float*)d_in[11];
    const float* bn1_b    = (const float*)d_in[12];
    const float* fc2_w    = (const float*)d_in[13];
    const float* fc2_b    = (const float*)d_in[14];
    const float* bn2_g    = (const float*)d_in[15];
    const float* bn2_b    = (const float*)d_in[16];
    const float* fc3_w    = (const float*)d_in[17];
    const float* fc3_b    = (const float*)d_in[18];
    float* out = (float*)d_out;

    cudaFuncSetAttribute(k_graph, cudaFuncAttributeMaxDynamicSharedMemorySize,
                         SMEM_BYTES);

    k_gemm<<<NN/128, 128>>>(x, W, att_src, att_dst);
    k_graph<<<NB, 512, SMEM_BYTES>>>(edge_idx, gat_bias, pool_w,
                                     fc1_w, fc1_b, bn1_g, bn1_b,
                                     fc2_w, fc2_b, bn2_g, bn2_b,
                                     fc3_w, fc3_b, out);
}

// round 9
// speedup vs baseline: 1.1111x; 1.1111x over previous
#include <cuda_runtime.h>
#include <math.h>

// ---------------- problem constants ----------------
#define NB     256                 // graphs per batch
#define G      400                 // nodes per graph
#define DEG    32                  // avg degree
#define INDIM  400
#define D1     32
#define KSEL   200                 // top-k kept nodes
#define EPG    (G*DEG)             // 12800 edges per graph
#define NN     (NB*G)              // 102400 nodes
#define ETOTLL ((long long)NB*(long long)EPG)  // 3276800 edges
#define SLOPE  0.2f
#define BN_SCL 0.99999499987f      // 1/sqrt(1+1e-5)
#define CAP    64                  // per-dst bin capacity (max deg ~60 incl self)

// output layout (float32): logits[NB*2] | pool_w[32] | sig(vals)[NB*K] | perm[NB*K]
#define OFF_POOLW (NB*2)               // 512
#define OFF_SIG   (OFF_POOLW + D1)     // 544
#define OFF_PERM  (OFF_SIG + NB*KSEL)  // 51744

// ---------------- scratch (module-static, no runtime alloc) ----------------
__device__ float g_h[(size_t)NN*D1];     // 13.1 MB
__device__ float g_out_buf[(size_t)NN*D1];
__device__ float g_as[NN];
__device__ float g_ad[NN];

// ---------------- index dtype handling ----------------
__device__ __forceinline__ int detect_is64(const void* p) {
    const int* w = (const int*)p;
    int any = 0;
#pragma unroll
    for (int j = 1; j <= 15; j += 2) any |= w[j];
    return any == 0;
}
__device__ __forceinline__ int load_idx(const void* p, long long i, int is64) {
    return is64 ? (int)((const long long*)p)[i] : ((const int*)p)[i];
}

// ---------------- f32x2 + cp.async helpers ----------------
typedef unsigned long long u64t;
__device__ __forceinline__ void fma2(u64t& d, u64t a, u64t b) {
    asm volatile("fma.rn.f32x2 %0, %1, %2, %0;" : "+l"(d) : "l"(a), "l"(b));
}
__device__ __forceinline__ u64t pack2(float lo, float hi) {
    u64t r;
    asm("mov.b64 %0, {%1, %2};" : "=l"(r) : "f"(lo), "f"(hi));
    return r;
}
__device__ __forceinline__ void unpack2(u64t v, float& lo, float& hi) {
    asm("mov.b64 {%0, %1}, %2;" : "=f"(lo), "=f"(hi) : "l"(v));
}
__device__ __forceinline__ void cpa4(float* s, const float* g) {
    unsigned sa = (unsigned)__cvta_generic_to_shared(s);
    asm volatile("cp.async.ca.shared.global [%0], [%1], 4;" :: "r"(sa), "l"(g));
}
__device__ __forceinline__ void cpa16(void* s, const void* g) {
    unsigned sa = (unsigned)__cvta_generic_to_shared(s);
    asm volatile("cp.async.cg.shared.global [%0], [%1], 16;" :: "r"(sa), "l"(g));
}
__device__ __forceinline__ void cpa_commit() {
    asm volatile("cp.async.commit_group;");
}
template <int N> __device__ __forceinline__ void cpa_wait() {
    asm volatile("cp.async.wait_group %0;" :: "n"(N));
}

// ============================================================================
// K1: h = x @ W (+ a_src, a_dst).  FFMA2 + cp.async, 128 rows/CTA (round 8).
// At the fp32-datapath roofline; unchanged.
// ============================================================================
#define KC    16
#define ASTR  130
__global__ __launch_bounds__(128) void k_gemm(
    const float* __restrict__ x, const float* __restrict__ W,
    const float* __restrict__ att_src, const float* __restrict__ att_dst)
{
    __shared__ float shA[2][KC*ASTR];
    __shared__ float shB[2][KC*32];

    const int t  = threadIdx.x;
    const int tc = t & 7;
    const int tr = t >> 3;
    const size_t row0 = (size_t)blockIdx.x * 128;

    const int lkk = t & 15, lr = t >> 4;
    const float* xbase = x + (row0 + lr) * INDIM + lkk;
    const int bkk = t >> 3, bc = (t & 7) * 4;

    u64t acc[4][4];
#pragma unroll
    for (int r = 0; r < 4; ++r)
#pragma unroll
        for (int c = 0; c < 4; ++c) acc[r][c] = 0ull;

    {
#pragma unroll
        for (int j = 0; j < 16; ++j)
            cpa4(&shA[0][lkk*ASTR + lr + 8*j], xbase + (size_t)(8*j) * INDIM);
        cpa16(&shB[0][bkk*32 + bc], W + (size_t)bkk * 32 + bc);
        cpa_commit();
    }

    int buf = 0;
#pragma unroll 1
    for (int c = 0; c < INDIM/KC; ++c) {
        if (c + 1 < INDIM/KC) {
            const float* src = xbase + (size_t)(c + 1) * KC;
#pragma unroll
            for (int j = 0; j < 16; ++j)
                cpa4(&shA[buf^1][lkk*ASTR + lr + 8*j], src + (size_t)(8*j) * INDIM);
            cpa16(&shB[buf^1][bkk*32 + bc], W + (size_t)((c+1)*KC + bkk) * 32 + bc);
            cpa_commit();
            cpa_wait<1>();
        } else {
            cpa_wait<0>();
        }
        __syncthreads();

        const float* A = shA[buf];
        const float* B = shB[buf];
#pragma unroll
        for (int kk = 0; kk < KC; ++kk) {
            float4 b = *(const float4*)(B + kk*32 + tc*4);
            u64t bp0 = pack2(b.x, b.x);
            u64t bp1 = pack2(b.y, b.y);
            u64t bp2 = pack2(b.z, b.z);
            u64t bp3 = pack2(b.w, b.w);
            const float* Ak = A + kk*ASTR + tr*8;
#pragma unroll
            for (int r = 0; r < 4; ++r) {
                u64t a = *(const u64t*)(Ak + 2*r);
                fma2(acc[r][0], a, bp0);
                fma2(acc[r][1], a, bp1);
                fma2(acc[r][2], a, bp2);
                fma2(acc[r][3], a, bp3);
            }
        }
        __syncthreads();
        buf ^= 1;
    }

    float4 aS = ((const float4*)att_src)[tc];
    float4 aD = ((const float4*)att_dst)[tc];
#pragma unroll
    for (int r = 0; r < 4; ++r) {
        float l0, h0, l1, h1, l2, h2, l3, h3;
        unpack2(acc[r][0], l0, h0);
        unpack2(acc[r][1], l1, h1);
        unpack2(acc[r][2], l2, h2);
        unpack2(acc[r][3], l3, h3);
#pragma unroll
        for (int half = 0; half < 2; ++half) {
            float v0 = half ? h0 : l0, v1 = half ? h1 : l1;
            float v2 = half ? h2 : l2, v3 = half ? h3 : l3;
            size_t row = row0 + tr*8 + 2*r + half;
            *(float4*)&g_h[row*D1 + tc*4] = make_float4(v0, v1, v2, v3);
            float ps = v0*aS.x + v1*aS.y + v2*aS.z + v3*aS.w;
            float pd = v0*aD.x + v1*aD.y + v2*aD.z + v3*aD.w;
#pragma unroll
            for (int d = 4; d >= 1; d >>= 1) {
                ps += __shfl_down_sync(0xffffffffu, ps, d, 8);
                pd += __shfl_down_sync(0xffffffffu, pd, d, 8);
            }
            if (tc == 0) { g_as[row] = ps; g_ad[row] = pd; }
        }
    }
}

// ============================================================================
// K2: per-graph GAT + TopK + MLP. Round-7 convergent structure; inner loop
// fully unrolled to 8 fixed iterations (zero-padded alpha) with dual
// accumulator pairs for ILP. No per-chunk trip-count shuffles.
// ============================================================================
#define O_H    0        // 12800 f
#define O_SRC  12800    // 400*CAP u16 = 12800 words
#define O_CNT  25600    // 400 i
#define O_AS   26000    // 400 f
#define O_AD   26400    // 400 f
#define O_SV   26800    // 512 f
#define O_SI   27312    // 512 i
// aliases (valid after aggregation finishes with sh_src):
#define O_PM   12800    // 512 f
#define O_PS   13312    // 512 f
#define O_Z    13824    // 64 f
#define O_Z1   13888    // 32 f
#define O_Z2   13920    // 8 f
#define SMEM_WORDS 27824
#define SMEM_BYTES (SMEM_WORDS*4)

__global__ __launch_bounds__(512, 2) void k_graph(
    const void* __restrict__ edge_index,
    const float* __restrict__ gat_bias, const float* __restrict__ pool_w,
    const float* __restrict__ fc1_w, const float* __restrict__ fc1_b,
    const float* __restrict__ bn1_g, const float* __restrict__ bn1_b,
    const float* __restrict__ fc2_w, const float* __restrict__ fc2_b,
    const float* __restrict__ bn2_g, const float* __restrict__ bn2_b,
    const float* __restrict__ fc3_w, const float* __restrict__ fc3_b,
    float* __restrict__ out)
{
    extern __shared__ float sm[];
    float* sh_h   = sm + O_H;
    unsigned short* sh_src = (unsigned short*)(sm + O_SRC);
    int*   sh_cnt = (int*)(sm + O_CNT);
    float* sh_as  = sm + O_AS;
    float* sh_ad  = sm + O_AD;
    float* sh_sv  = sm + O_SV;
    int*   sh_si  = (int*)(sm + O_SI);
    float* sh_pm  = sm + O_PM;
    float* sh_ps  = sm + O_PS;
    float* sh_z   = sm + O_Z;
    float* sh_z1  = sm + O_Z1;
    float* sh_z2  = sm + O_Z2;

    const int b    = blockIdx.x;
    const int t    = threadIdx.x;
    const int lane = t & 31;
    const int w    = t >> 5;
    const int qu   = lane >> 3;    // quarter 0..3
    const int ql   = lane & 7;     // lane in quarter
    const int base = b * G;
    const int is64 = detect_is64(edge_index);
    const long long e0 = (long long)b * EPG;
    const unsigned FULL = 0xffffffffu;

    // ---- phase 1: h staging via cp.async; init cnt/as/ad/self ----
    {
        const float4* H4 = (const float4*)(g_h + (size_t)base * D1);
        float4* S4 = (float4*)sh_h;
        for (int i = t; i < G*D1/4; i += 512) cpa16(&S4[i], &H4[i]);
        cpa_commit();
        for (int i = t; i < G; i += 512) {
            sh_as[i] = g_as[base + i];
            sh_ad[i] = g_ad[base + i];
            sh_cnt[i] = 1;
            sh_src[i * CAP] = (unsigned short)i;   // self loop in slot 0
        }
    }
    __syncthreads();

    // ---- phase 2: single-pass binned scatter (overlaps h cp.async) ----
    for (int i = t; i < EPG; i += 512) {
        int s = load_idx(edge_index, e0 + i, is64) - base;
        int d = load_idx(edge_index, ETOTLL + e0 + i, is64) - base;
        int p = atomicAdd(&sh_cnt[d], 1) & (CAP - 1);
        sh_src[d * CAP + p] = (unsigned short)s;
    }
    cpa_wait<0>();
    __syncthreads();

    // ---- phase 3: fused softmax+aggregation+score, 4 dsts/warp ----
    {
        float pwl = pool_w[lane];
        float n2 = pwl * pwl;
#pragma unroll
        for (int d = 16; d >= 1; d >>= 1) n2 += __shfl_xor_sync(FULL, n2, d);
        float invn = rsqrtf(n2);
        float4 pw4 = *(const float4*)&pool_w[4*ql];
        float4 gb4 = *(const float4*)&gat_bias[4*ql];

        for (int vq = 4*w; vq < G; vq += 64) {
            int v = vq + qu;
            int s1 = sh_cnt[v]; if (s1 > CAP) s1 = CAP;
            float ad = sh_ad[v];
            const unsigned short* srcp = sh_src + v * CAP;
            u64t accA0 = 0ull, accB0 = 0ull, accA1 = 0ull, accB1 = 0ull;
            float denl = 0.f;
            int ncm = (s1 + 7) >> 3;                 // warp-uniformize:
            ncm = max(ncm, __shfl_xor_sync(FULL, ncm, 8));
            ncm = max(ncm, __shfl_xor_sync(FULL, ncm, 16));
#pragma unroll 1
            for (int c = 0; c < ncm; ++c) {
                int i = (c << 3) + ql;
                float alpha = 0.f; int s = 0;
                if (i < s1) {
                    s = srcp[i];
                    float e = sh_as[s] + ad;
                    e = (e > 0.f) ? e : SLOPE * e;
                    alpha = __expf(e);
                }
                denl += alpha;
                // fixed 8 iterations: padded alpha contributes exactly 0.
#pragma unroll
                for (int ii = 0; ii < 8; ii += 2) {
                    float a0 = __shfl_sync(FULL, alpha, ii,     8);
                    int  ss0 = __shfl_sync(FULL, s,     ii,     8);
                    float a1 = __shfl_sync(FULL, alpha, ii + 1, 8);
                    int  ss1 = __shfl_sync(FULL, s,     ii + 1, 8);
                    u64t a20 = pack2(a0, a0);
                    u64t a21 = pack2(a1, a1);
                    ulonglong2 hv0 = *(const ulonglong2*)&sh_h[(ss0 << 5) + (ql << 2)];
                    ulonglong2 hv1 = *(const ulonglong2*)&sh_h[(ss1 << 5) + (ql << 2)];
                    fma2(accA0, hv0.x, a20);
                    fma2(accB0, hv0.y, a20);
                    fma2(accA1, hv1.x, a21);
                    fma2(accB1, hv1.y, a21);
                }
            }
            const u64t ONE2 = pack2(1.f, 1.f);
            fma2(accA0, accA1, ONE2);               // accA0 += accA1 (exact)
            fma2(accB0, accB1, ONE2);
            float den = denl;
            den += __shfl_xor_sync(FULL, den, 4, 8);
            den += __shfl_xor_sync(FULL, den, 2, 8);
            den += __shfl_xor_sync(FULL, den, 1, 8);
            float inv = 1.f / den;
            u64t i2 = pack2(inv, inv);
            u64t oA = pack2(gb4.x, gb4.y); fma2(oA, accA0, i2);
            u64t oB = pack2(gb4.z, gb4.w); fma2(oB, accB0, i2);
            float o0, o1, o2v, o3;
            unpack2(oA, o0, o1); unpack2(oB, o2v, o3);
            *(float4*)&g_out_buf[(size_t)(base + v) * D1 + (ql << 2)] =
                make_float4(o0, o1, o2v, o3);
            float p = o0*pw4.x + o1*pw4.y + o2v*pw4.z + o3*pw4.w;
            p += __shfl_xor_sync(FULL, p, 4, 8);
            p += __shfl_xor_sync(FULL, p, 2, 8);
            p += __shfl_xor_sync(FULL, p, 1, 8);
            if (ql == 0) {
                float sc = p * invn;
                sh_sv[v] = 1.f / (1.f + __expf(-sc));
                sh_si[v] = v;
            }
        }
    }
    if (t >= G) { sh_sv[t] = -1.f; sh_si[t] = t; }
    __syncthreads();

    // ---- bitonic sort, 512, descending value / ascending index ----
    for (int k = 2; k <= 512; k <<= 1) {
        for (int j = k >> 1; j > 0; j >>= 1) {
            int ixj = t ^ j;
            if (ixj > t) {
                float va = sh_sv[t], vb = sh_sv[ixj];
                int   ia = sh_si[t], ib = sh_si[ixj];
                bool before = (va > vb) || (va == vb && ia < ib);
                bool doswap = ((t & k) == 0) ? !before : before;
                if (doswap) {
                    sh_sv[t] = vb; sh_sv[ixj] = va;
                    sh_si[t] = ib; sh_si[ixj] = ia;
                }
            }
            __syncthreads();
        }
    }

    // ---- emit sig(vals) and perm ----
    for (int i = t; i < KSEL; i += 512) {
        float v = sh_sv[i];
        out[OFF_SIG  + b * KSEL + i] = 1.f / (1.f + __expf(-v));
        out[OFF_PERM + b * KSEL + i] = (float)(sh_si[i] + base);
    }

    // ---- global max/mean pool over selected scaled rows ----
    {
        float mx = -1e30f, smv = 0.f;
        for (int j = w; j < KSEL; j += 16) {
            float wt = sh_sv[j];
            float val = g_out_buf[(size_t)(base + sh_si[j]) * D1 + lane] * wt;
            mx = fmaxf(mx, val);
            smv += val;
        }
        sh_pm[w * 32 + lane] = mx;
        sh_ps[w * 32 + lane] = smv;
    }
    __syncthreads();
    if (t < D1) {
        float mx = -1e30f, smv = 0.f;
#pragma unroll
        for (int j = 0; j < 16; ++j) {
            mx = fmaxf(mx, sh_pm[j * 32 + t]);
            smv += sh_ps[j * 32 + t];
        }
        sh_z[t]      = mx;
        sh_z[D1 + t] = smv * (1.f / (float)KSEL);
    }
    __syncthreads();

    // ---- MLP tail (warp 0) ----
    if (w == 0) {
        float acc = fc1_b[lane];
        for (int i = 0; i < 2*D1; ++i) acc += sh_z[i] * fc1_w[i * D1 + lane];
        acc = fmaxf(acc, 0.f);
        acc = acc * (bn1_g[lane] * BN_SCL) + bn1_b[lane];
        sh_z1[lane] = acc;
        __syncwarp();
        if (lane < 8) {
            float y = fc2_b[lane];
            for (int i = 0; i < D1; ++i) y += sh_z1[i] * fc2_w[i * 8 + lane];
            y = fmaxf(y, 0.f);
            y = y * (bn2_g[lane] * BN_SCL) + bn2_b[lane];
            sh_z2[lane] = y;
        }
        __syncwarp();
        if (lane < 2) {
            float y = fc3_b[lane];
            for (int i = 0; i < 8; ++i) y += sh_z2[i] * fc3_w[i * 2 + lane];
            float other = __shfl_xor_sync(0x3u, y, 1, 2);
            float m = fmaxf(y, other);
            float lse = m + logf(expf(y - m) + expf(other - m));
            out[b * 2 + lane] = y - lse;
        }
    }

    if (b == 0 && t < D1) out[OFF_POOLW + t] = pool_w[t];
}

// ============================================================================
extern "C" void kernel_launch(void* const* d_in, const int* in_sizes, int n_in,
                              void* d_out, int out_size)
{
    const float* x        = (const float*)d_in[0];
    const void*  edge_idx = d_in[1];
    const float* W        = (const float*)d_in[4];
    const float* att_src  = (const float*)d_in[5];
    const float* att_dst  = (const float*)d_in[6];
    const float* gat_bias = (const float*)d_in[7];
    const float* pool_w   = (const float*)d_in[8];
    const float* fc1_w    = (const float*)d_in[9];
    const float* fc1_b    = (const float*)d_in[10];
    const float* bn1_g    = (const float*)d_in[11];
    const float* bn1_b    = (const float*)d_in[12];
    const float* fc2_w    = (const float*)d_in[13];
    const float* fc2_b    = (const float*)d_in[14];
    const float* bn2_g    = (const float*)d_in[15];
    const float* bn2_b    = (const float*)d_in[16];
    const float* fc3_w    = (const float*)d_in[17];
    const float* fc3_b    = (const float*)d_in[18];
    float* out = (float*)d_out;

    cudaFuncSetAttribute(k_graph, cudaFuncAttributeMaxDynamicSharedMemorySize,
                         SMEM_BYTES);

    k_gemm<<<NN/128, 128>>>(x, W, att_src, att_dst);
    k_graph<<<NB, 512, SMEM_BYTES>>>(edge_idx, gat_bias, pool_w,
                                     fc1_w, fc1_b, bn1_g, bn1_b,
                                     fc2_w, fc2_b, bn2_g, bn2_b,
                                     fc3_w, fc3_b, out);
}